// round 6
// baseline (speedup 1.0000x reference)
#include <cuda_runtime.h>
#include <cstdint>

// Problem constants
#define N_TOTAL   32768      // 32 * 32 * 32 rows
#define DIM       256        // embedding dim
#define KCODES    1024       // codebook size

// Tiling
#define BR        64         // rows per CTA
#define THREADS   256        // 8 warps
#define ZS_STRIDE 72         // zs[d][r] row stride (conflict-free A loads)
#define WS_STRIDE 130        // ws2[k][c] row stride in float2 units
#define SK        32         // k-depth staged per sync

// Output layout (tuple flattened in order)
#define QOUT_ELEMS   (32 * DIM * 32 * 32)   // 8388608
#define LOSS_ELEMS   N_TOTAL                // 32768

__device__ float g_wsq[KCODES];
__device__ float g_zsq[N_TOTAL];

__device__ __forceinline__ float to_tf32(float x) {
    uint32_t u;
    asm("cvt.rna.tf32.f32 %0, %1;" : "=r"(u) : "f"(x));
    return __uint_as_float(u);
}
__device__ __forceinline__ uint32_t to_tf32_bits(float x) {
    uint32_t u;
    asm("cvt.rna.tf32.f32 %0, %1;" : "=r"(u) : "f"(x));
    return u;
}

// m16n8k8 tf32 mma: D = A*B + D (fp32 accum)
__device__ __forceinline__ void mma_tf32(float* c, const uint32_t* a,
                                         uint32_t b0, uint32_t b1) {
    asm volatile(
        "mma.sync.aligned.m16n8k8.row.col.f32.tf32.tf32.f32 "
        "{%0,%1,%2,%3}, {%4,%5,%6,%7}, {%8,%9}, {%0,%1,%2,%3};"
        : "+f"(c[0]), "+f"(c[1]), "+f"(c[2]), "+f"(c[3])
        : "r"(a[0]), "r"(a[1]), "r"(a[2]), "r"(a[3]), "r"(b0), "r"(b1));
}

// ---------------------------------------------------------------------------
// wsq[k] = sum_d w[d][k]^2
// ---------------------------------------------------------------------------
__global__ void __launch_bounds__(256)
wsq_kernel(const float* __restrict__ w) {
    __shared__ float red[8][32];
    const int tx = threadIdx.x;
    const int ty = threadIdx.y;
    const int k = blockIdx.x * 32 + tx;
    float s = 0.f;
#pragma unroll
    for (int i = 0; i < 32; i++) {
        float v = w[(size_t)(ty + 8 * i) * KCODES + k];
        s = __fadd_rn(s, __fmul_rn(v, v));
    }
    red[ty][tx] = s;
    __syncthreads();
    if (ty == 0) {
        float t = red[0][tx];
#pragma unroll
        for (int j = 1; j < 8; j++) t = __fadd_rn(t, red[j][tx]);
        g_wsq[k] = t;
    }
}

// ---------------------------------------------------------------------------
// zsq[n] = sum_d z[n,d]^2 (grid-shift invariant: exact order irrelevant)
// ---------------------------------------------------------------------------
__global__ void __launch_bounds__(1024)
zsq_kernel(const float* __restrict__ z) {
    __shared__ float sp[32][33];
    const int tx = threadIdx.x;
    const int ty = threadIdx.y;
    const int n0 = blockIdx.x * 32;
    const int b  = n0 >> 10;
    const int hw = (n0 & 1023) + tx;

    const float* zb = z + ((size_t)(b * DIM) << 10) + hw;
    float p = 0.f;
#pragma unroll
    for (int i = 0; i < 8; i++) {
        float v = zb[(size_t)(ty + 32 * i) << 10];
        p = __fadd_rn(p, __fmul_rn(v, v));
    }
    sp[ty][tx] = p;
    __syncthreads();

    float val = sp[tx][ty];
#pragma unroll
    for (int off = 16; off >= 1; off >>= 1)
        val = __fadd_rn(val, __shfl_down_sync(0xffffffffu, val, off));
    if (tx == 0) g_zsq[n0 + ty] = val;
}

// ---------------------------------------------------------------------------
// Fused: tf32 3-split tensor-core distance GEMM + HLO-exact score bucketing
//        + argmin + gather + straight-through output + losses.
// 8 warps: warp = (warp&1) rowgroup of 32 rows x (warp>>1) colgroup of 32 cols
// per 128-col k-tile.  2 mtiles x 4 ntiles per warp, 3 mma per (mtile,ntile).
// ---------------------------------------------------------------------------
__global__ void __launch_bounds__(THREADS, 2)
vq_kernel(const float* __restrict__ z, const float* __restrict__ w,
          float* __restrict__ qout, float* __restrict__ loss,
          float* __restrict__ commit, float* __restrict__ embed) {
    extern __shared__ float sm[];
    float*  zs  = sm;                               // [DIM][ZS_STRIDE]
    float2* ws2 = (float2*)(sm + DIM * ZS_STRIDE);  // [SK][WS_STRIDE] (hi,lo)
    // aliases into the ws2 region, used only after the GEMM loop:
    float* sredv   = (float*)ws2;                   // [64][4]
    int*   sredi   = (int*)(sredv + 256);           // [64][4]
    int*   srowidx = (int*)(sredi + 256);           // [64]
    float* part    = (float*)ws2 + 768;             // [256]

    const int tid  = threadIdx.x;
    const int warp = tid >> 5;
    const int lane = tid & 31;
    const int wr = (warp & 1) * 32;     // warp row offset
    const int wc = (warp >> 1) * 32;    // warp col offset within k-tile
    const int lg = lane >> 2;           // fragment row group 0..7
    const int lt = lane & 3;            // fragment thread-in-group 0..3

    const int n0  = blockIdx.x * BR;
    const int b   = n0 >> 10;
    const int hw0 = n0 & 1023;
    const float* zbase = z + ((size_t)(b * DIM) << 10) + hw0;

    // ---- Load z tile: zs[d][r] (original fp32, kept for epilogue) ----
    {
        for (int i = tid; i < DIM * 16; i += THREADS) {
            int d = i / 16, f = i % 16;
            float4 v = *(const float4*)(zbase + ((size_t)d << 10) + f * 4);
            *(float4*)(zs + d * ZS_STRIDE + f * 4) = v;
        }
    }

    // Thread's 4 fragment rows (mi in 0..1, h in 0..1): row = wr+mi*16+h*8+lg
    float tzsq[4];
    float bestv[4];
    int   besti[4];
#pragma unroll
    for (int mi = 0; mi < 2; mi++)
#pragma unroll
        for (int h = 0; h < 2; h++) {
            int idx = mi * 2 + h;
            tzsq[idx] = g_zsq[n0 + wr + mi * 16 + h * 8 + lg];
            bestv[idx] = 3.4e38f;
            besti[idx] = 0;
        }

    // ---- Main loop: 8 k-tiles of 128 cols ----
    for (int kt = 0; kt < 8; kt++) {
        float acc[2][4][4];
#pragma unroll
        for (int mi = 0; mi < 2; mi++)
#pragma unroll
            for (int ni = 0; ni < 4; ni++)
#pragma unroll
                for (int q = 0; q < 4; q++) acc[mi][ni][q] = 0.f;

        for (int stage = 0; stage < DIM / SK; stage++) {
            __syncthreads();   // previous ws2 consumers done (covers zs 1st time)
            // stage w slab [SK][128] as (hi,lo) float2
            for (int i = tid; i < SK * 128; i += THREADS) {
                int kk = i >> 7, c = i & 127;
                float v = w[(size_t)(stage * SK + kk) * KCODES + kt * 128 + c];
                float hi = to_tf32(v);
                float lo = to_tf32(__fsub_rn(v, hi));
                ws2[kk * WS_STRIDE + c] = make_float2(hi, lo);
            }
            __syncthreads();

#pragma unroll
            for (int cc = 0; cc < 4; cc++) {       // 4 k-chunks of 8
                const int d0 = stage * SK + cc * 8 + lt;
                // A fragments (hi and lo) for 2 mtiles
                uint32_t ah[2][4], al[2][4];
#pragma unroll
                for (int mi = 0; mi < 2; mi++) {
                    const int r = wr + mi * 16 + lg;
                    float v0 = zs[d0 * ZS_STRIDE + r];
                    float v1 = zs[d0 * ZS_STRIDE + r + 8];
                    float v2 = zs[(d0 + 4) * ZS_STRIDE + r];
                    float v3 = zs[(d0 + 4) * ZS_STRIDE + r + 8];
                    ah[mi][0] = to_tf32_bits(v0);
                    ah[mi][1] = to_tf32_bits(v1);
                    ah[mi][2] = to_tf32_bits(v2);
                    ah[mi][3] = to_tf32_bits(v3);
                    al[mi][0] = to_tf32_bits(__fsub_rn(v0, __uint_as_float(ah[mi][0])));
                    al[mi][1] = to_tf32_bits(__fsub_rn(v1, __uint_as_float(ah[mi][1])));
                    al[mi][2] = to_tf32_bits(__fsub_rn(v2, __uint_as_float(ah[mi][2])));
                    al[mi][3] = to_tf32_bits(__fsub_rn(v3, __uint_as_float(ah[mi][3])));
                }
#pragma unroll
                for (int ni = 0; ni < 4; ni++) {
                    // B fragment (hi,lo together via LDS.64)
                    float2 b0 = ws2[(cc * 8 + lt) * WS_STRIDE + wc + ni * 8 + lg];
                    float2 b1 = ws2[(cc * 8 + lt + 4) * WS_STRIDE + wc + ni * 8 + lg];
                    uint32_t b0h = __float_as_uint(b0.x), b0l = __float_as_uint(b0.y);
                    uint32_t b1h = __float_as_uint(b1.x), b1l = __float_as_uint(b1.y);
#pragma unroll
                    for (int mi = 0; mi < 2; mi++) {
                        mma_tf32(acc[mi][ni], al[mi], b0h, b1h);   // lo*hi
                        mma_tf32(acc[mi][ni], ah[mi], b0l, b1l);   // hi*lo
                        mma_tf32(acc[mi][ni], ah[mi], b0h, b1h);   // hi*hi
                    }
                }
            }
        }

        // ---- scores: s = fl(fl(zsq + wsq) - 2*dot); running argmin ----
#pragma unroll
        for (int ni = 0; ni < 4; ni++) {
            const int col0 = kt * 128 + wc + ni * 8 + lt * 2;
            const float wq0 = __ldg(&g_wsq[col0]);
            const float wq1 = __ldg(&g_wsq[col0 + 1]);
#pragma unroll
            for (int mi = 0; mi < 2; mi++)
#pragma unroll
                for (int h = 0; h < 2; h++) {
                    const int idx = mi * 2 + h;
                    float d0v = acc[mi][ni][h * 2 + 0];
                    float d1v = acc[mi][ni][h * 2 + 1];
                    float s0 = __fsub_rn(__fadd_rn(tzsq[idx], wq0),
                                         __fmul_rn(2.f, d0v));
                    float s1 = __fsub_rn(__fadd_rn(tzsq[idx], wq1),
                                         __fmul_rn(2.f, d1v));
                    if (s0 < bestv[idx]) { bestv[idx] = s0; besti[idx] = col0; }
                    if (s1 < bestv[idx]) { bestv[idx] = s1; besti[idx] = col0 + 1; }
                }
        }
    }

    __syncthreads();   // all warps done reading ws2 before aliasing as scratch

    // ---- reduce over the 4 lanes (lt) sharing each fragment row ----
#pragma unroll
    for (int mi = 0; mi < 2; mi++)
#pragma unroll
        for (int h = 0; h < 2; h++) {
            const int idx = mi * 2 + h;
            float v = bestv[idx];
            int   i = besti[idx];
#pragma unroll
            for (int off = 1; off <= 2; off <<= 1) {
                float v2 = __shfl_xor_sync(0xffffffffu, v, off);
                int   i2 = __shfl_xor_sync(0xffffffffu, i, off);
                if (v2 < v || (v2 == v && i2 < i)) { v = v2; i = i2; }
            }
            if (lt == 0) {
                const int row = wr + mi * 16 + h * 8 + lg;
                sredv[row * 4 + (warp >> 1)] = v;
                sredi[row * 4 + (warp >> 1)] = i;
            }
        }
    __syncthreads();

    // ---- final reduce over the 4 colgroups ----
    if (tid < 64) {
        float v = sredv[tid * 4];
        int   i = sredi[tid * 4];
#pragma unroll
        for (int g = 1; g < 4; g++) {
            float v2 = sredv[tid * 4 + g];
            int   i2 = sredi[tid * 4 + g];
            if (v2 < v || (v2 == v && i2 < i)) { v = v2; i = i2; }
        }
        srowidx[tid] = i;
    }
    __syncthreads();

    // ---- Epilogue: gather winning code, write q_st + losses ----
    const int r  = tid & 63;
    const int dh = tid >> 6;      // 0..3
    const int kstar = srowidx[r];
    float partial = 0.f;
    float* qbase = qout + ((size_t)(b * DIM) << 10) + hw0;
#pragma unroll 4
    for (int d = dh; d < DIM; d += 4) {
        float wv = __ldg(w + (size_t)d * KCODES + kstar);
        float zv = zs[d * ZS_STRIDE + r];
        float diff = __fsub_rn(wv, zv);
        partial = __fmaf_rn(diff, diff, partial);
        qbase[((size_t)d << 10) + r] = __fadd_rn(zv, diff);  // z + (q - z)
    }

    __syncthreads();
    part[tid] = partial;
    __syncthreads();
    if (dh == 0) {
        float mse = (part[r] + part[64 + r] + part[128 + r] + part[192 + r])
                    * (1.0f / DIM);
        int n = n0 + r;
        commit[n] = mse;
        embed[n]  = mse;
        loss[n]   = __fadd_rn(__fmul_rn(0.25f, mse), mse);
    }
}

// ---------------------------------------------------------------------------
extern "C" void kernel_launch(void* const* d_in, const int* in_sizes, int n_in,
                              void* d_out, int out_size) {
    const float* z = (const float*)d_in[0];
    const float* w = (const float*)d_in[1];
    float* out    = (float*)d_out;
    float* qout   = out;
    float* loss   = out + QOUT_ELEMS;
    float* commit = loss + LOSS_ELEMS;
    float* embed  = commit + LOSS_ELEMS;

    wsq_kernel<<<KCODES / 32, dim3(32, 8)>>>(w);
    zsq_kernel<<<N_TOTAL / 32, dim3(32, 32)>>>(z);

    const size_t smem_bytes =
        (size_t)DIM * ZS_STRIDE * sizeof(float) +
        (size_t)SK * WS_STRIDE * sizeof(float2);
    static bool attr_set = false;
    if (!attr_set) {
        cudaFuncSetAttribute(vq_kernel, cudaFuncAttributeMaxDynamicSharedMemorySize,
                             (int)smem_bytes);
        attr_set = true;
    }
    vq_kernel<<<N_TOTAL / BR, THREADS, smem_bytes>>>(z, w, qout, loss, commit, embed);
}

// round 8
// speedup vs baseline: 1.3850x; 1.3850x over previous
#include <cuda_runtime.h>
#include <cstdint>
#include <cfloat>

// Problem constants
#define N_TOTAL   32768
#define DIM       256
#define KCODES    1024
#define BR        64          // rows per CTA
#define THREADS   256         // 8 warps
#define ZSTR      72          // zs row stride (floats)
#define WSTR      136         // ws row stride (floats), conflict-free (8*lt+lg)
#define CAP       32          // candidate capacity per row
#define EPSF      2e-3f       // rescue margin (>= 2x worst-case tf32 score error)

#define QOUT_ELEMS   (32 * DIM * 32 * 32)
#define LOSS_ELEMS   N_TOTAL

__device__ float g_wsq[KCODES];
__device__ float g_zsq[N_TOTAL];
__device__ float g_whi[DIM * KCODES];   // tf32-rounded w, [d][c]
__device__ float g_wT[KCODES * DIM];    // transposed original w, [c][d]

__device__ __forceinline__ float to_tf32(float x) {
    uint32_t u;
    asm("cvt.rna.tf32.f32 %0, %1;" : "=r"(u) : "f"(x));
    return __uint_as_float(u);
}
__device__ __forceinline__ uint32_t to_tf32_bits(float x) {
    uint32_t u;
    asm("cvt.rna.tf32.f32 %0, %1;" : "=r"(u) : "f"(x));
    return u;
}
// m16n8k8 tf32 mma: D = A*B + D (fp32 accum)
__device__ __forceinline__ void mma_tf32(float* c, const uint32_t* a,
                                         uint32_t b0, uint32_t b1) {
    asm volatile(
        "mma.sync.aligned.m16n8k8.row.col.f32.tf32.tf32.f32 "
        "{%0,%1,%2,%3}, {%4,%5,%6,%7}, {%8,%9}, {%0,%1,%2,%3};"
        : "+f"(c[0]), "+f"(c[1]), "+f"(c[2]), "+f"(c[3])
        : "r"(a[0]), "r"(a[1]), "r"(a[2]), "r"(a[3]), "r"(b0), "r"(b1));
}

// ---------------------------------------------------------------------------
// wsq[k] = sum_d w[d][k]^2
// ---------------------------------------------------------------------------
__global__ void __launch_bounds__(256)
wsq_kernel(const float* __restrict__ w) {
    __shared__ float red[8][32];
    const int tx = threadIdx.x, ty = threadIdx.y;
    const int k = blockIdx.x * 32 + tx;
    float s = 0.f;
#pragma unroll
    for (int i = 0; i < 32; i++) {
        float v = w[(size_t)(ty + 8 * i) * KCODES + k];
        s = __fadd_rn(s, __fmul_rn(v, v));
    }
    red[ty][tx] = s;
    __syncthreads();
    if (ty == 0) {
        float t = red[0][tx];
#pragma unroll
        for (int j = 1; j < 8; j++) t = __fadd_rn(t, red[j][tx]);
        g_wsq[k] = t;
    }
}

// ---------------------------------------------------------------------------
// w prep: g_whi = tf32(w) same layout; g_wT = transpose(w)
// grid (32, 8), block (32, 32)
// ---------------------------------------------------------------------------
__global__ void __launch_bounds__(1024)
wprep_kernel(const float* __restrict__ w) {
    __shared__ float t[32][33];
    const int tx = threadIdx.x, ty = threadIdx.y;
    const int c0 = blockIdx.x * 32, d0 = blockIdx.y * 32;
    float v = w[(size_t)(d0 + ty) * KCODES + c0 + tx];
    g_whi[(size_t)(d0 + ty) * KCODES + c0 + tx] = to_tf32(v);
    t[ty][tx] = v;
    __syncthreads();
    g_wT[(size_t)(c0 + ty) * DIM + d0 + tx] = t[tx][ty];
}

// ---------------------------------------------------------------------------
// zsq[n] = sum_d z[n,d]^2
// ---------------------------------------------------------------------------
__global__ void __launch_bounds__(1024)
zsq_kernel(const float* __restrict__ z) {
    __shared__ float sp[32][33];
    const int tx = threadIdx.x, ty = threadIdx.y;
    const int n0 = blockIdx.x * 32;
    const int b  = n0 >> 10;
    const int hw = (n0 & 1023) + tx;
    const float* zb = z + ((size_t)(b * DIM) << 10) + hw;
    float p = 0.f;
#pragma unroll
    for (int i = 0; i < 8; i++) {
        float v = zb[(size_t)(ty + 32 * i) << 10];
        p = __fadd_rn(p, __fmul_rn(v, v));
    }
    sp[ty][tx] = p;
    __syncthreads();
    float val = sp[tx][ty];
#pragma unroll
    for (int off = 16; off >= 1; off >>= 1)
        val = __fadd_rn(val, __shfl_down_sync(0xffffffffu, val, off));
    if (tx == 0) g_zsq[n0 + ty] = val;
}

// ---------------------------------------------------------------------------
// Fused: tf32 screening GEMM + conservative candidate collection
//        + exact fp32 rescue argmin + gather + q_st + losses.
// ---------------------------------------------------------------------------
__global__ void __launch_bounds__(THREADS, 2)
vq_kernel(const float* __restrict__ z, const float* __restrict__ w,
          float* __restrict__ qout, float* __restrict__ loss,
          float* __restrict__ commit, float* __restrict__ embed) {
    extern __shared__ float sm[];
    float* zs      = sm;                    // [DIM][ZSTR]   73728 B
    float* ws      = zs + DIM * ZSTR;       // [32][WSTR]    17408 B
    float* swsq    = ws + 32 * WSTR;        // [1024]
    int*   srowmin = (int*)(swsq + KCODES); // [64]
    int*   scount  = srowmin + BR;          // [64]
    int*   scand   = scount + BR;           // [64][CAP]
    int*   srowidx = scand + BR * CAP;      // [64]
    float* part    = (float*)(srowidx + BR);// [256]

    const int tid  = threadIdx.x;
    const int warp = tid >> 5;
    const int lane = tid & 31;
    const int wr = (warp & 1) * 32;
    const int wc = (warp >> 1) * 32;
    const int lg = lane >> 2;
    const int lt = lane & 3;

    const int n0  = blockIdx.x * BR;
    const int b   = n0 >> 10;
    const int hw0 = n0 & 1023;
    const float* zbase = z + ((size_t)(b * DIM) << 10) + hw0;

    // ---- Load z tile (original fp32) + wsq + init candidate state ----
    for (int i = tid; i < DIM * 16; i += THREADS) {
        int d = i / 16, f = i % 16;
        float4 v = *(const float4*)(zbase + ((size_t)d << 10) + f * 4);
        *(float4*)(zs + d * ZSTR + f * 4) = v;
    }
    for (int i = tid; i < KCODES; i += THREADS) swsq[i] = g_wsq[i];
    if (tid < BR) { srowmin[tid] = 0x7F7FFFFF; scount[tid] = 0; }

    float tzsq[4];
#pragma unroll
    for (int mi = 0; mi < 2; mi++)
#pragma unroll
        for (int h = 0; h < 2; h++)
            tzsq[mi * 2 + h] = g_zsq[n0 + wr + mi * 16 + h * 8 + lg];

    // ---- screening: 8 k-tiles of 128 codebook cols ----
    for (int kt = 0; kt < 8; kt++) {
        float acc[2][4][4];
#pragma unroll
        for (int mi = 0; mi < 2; mi++)
#pragma unroll
            for (int ni = 0; ni < 4; ni++)
#pragma unroll
                for (int q = 0; q < 4; q++) acc[mi][ni][q] = 0.f;

        for (int stage = 0; stage < 8; stage++) {
            __syncthreads();  // prior ws readers done (also covers zs/init 1st time)
            // stage pre-rounded w slab [32][128]
            for (int i = tid; i < 32 * 128; i += THREADS) {
                int kk = i >> 7, c = i & 127;
                ws[kk * WSTR + c] =
                    g_whi[(size_t)(stage * 32 + kk) * KCODES + kt * 128 + c];
            }
            __syncthreads();

#pragma unroll
            for (int cc = 0; cc < 4; cc++) {
                const int d0 = stage * 32 + cc * 8 + lt;
                uint32_t ah[2][4];
#pragma unroll
                for (int mi = 0; mi < 2; mi++) {
                    const int r = wr + mi * 16 + lg;
                    ah[mi][0] = to_tf32_bits(zs[d0 * ZSTR + r]);
                    ah[mi][1] = to_tf32_bits(zs[d0 * ZSTR + r + 8]);
                    ah[mi][2] = to_tf32_bits(zs[(d0 + 4) * ZSTR + r]);
                    ah[mi][3] = to_tf32_bits(zs[(d0 + 4) * ZSTR + r + 8]);
                }
#pragma unroll
                for (int ni = 0; ni < 4; ni++) {
                    uint32_t b0 = __float_as_uint(
                        ws[(cc * 8 + lt) * WSTR + wc + ni * 8 + lg]);
                    uint32_t b1 = __float_as_uint(
                        ws[(cc * 8 + lt + 4) * WSTR + wc + ni * 8 + lg]);
                    mma_tf32(acc[0][ni], ah[0], b0, b1);
                    mma_tf32(acc[1][ni], ah[1], b0, b1);
                }
            }
        }

        // pass 1: per-row screened min (running, conservative)
#pragma unroll
        for (int mi = 0; mi < 2; mi++)
#pragma unroll
            for (int h = 0; h < 2; h++) {
                const int idx = mi * 2 + h;
                float rm = FLT_MAX;
#pragma unroll
                for (int ni = 0; ni < 4; ni++) {
                    const int col0 = kt * 128 + wc + ni * 8 + lt * 2;
                    float s0 = __fsub_rn(__fadd_rn(tzsq[idx], swsq[col0]),
                                         __fmul_rn(2.f, acc[mi][ni][h * 2]));
                    float s1 = __fsub_rn(__fadd_rn(tzsq[idx], swsq[col0 + 1]),
                                         __fmul_rn(2.f, acc[mi][ni][h * 2 + 1]));
                    rm = fminf(rm, fminf(s0, s1));
                }
                atomicMin(&srowmin[wr + mi * 16 + h * 8 + lg],
                          __float_as_int(rm));
            }
        __syncthreads();

        // pass 2: collect candidates <= running row min + EPS
#pragma unroll
        for (int mi = 0; mi < 2; mi++)
#pragma unroll
            for (int h = 0; h < 2; h++) {
                const int idx = mi * 2 + h;
                const int row = wr + mi * 16 + h * 8 + lg;
                const float thr = __int_as_float(srowmin[row]) + EPSF;
#pragma unroll
                for (int ni = 0; ni < 4; ni++) {
                    const int col0 = kt * 128 + wc + ni * 8 + lt * 2;
                    float s0 = __fsub_rn(__fadd_rn(tzsq[idx], swsq[col0]),
                                         __fmul_rn(2.f, acc[mi][ni][h * 2]));
                    float s1 = __fsub_rn(__fadd_rn(tzsq[idx], swsq[col0 + 1]),
                                         __fmul_rn(2.f, acc[mi][ni][h * 2 + 1]));
                    if (s0 <= thr) {
                        int p = atomicAdd(&scount[row], 1);
                        if (p < CAP) scand[row * CAP + p] = col0;
                    }
                    if (s1 <= thr) {
                        int p = atomicAdd(&scount[row], 1);
                        if (p < CAP) scand[row * CAP + p] = col0 + 1;
                    }
                }
            }
    }
    __syncthreads();

    // ---- exact rescue: 4 threads per row re-score candidates in fp32 ----
    {
        const int row = tid >> 2;
        const int t4  = tid & 3;
        const int cnt = scount[row];
        const float zsqr = g_zsq[n0 + row];
        float bv = FLT_MAX;
        int   bi = 0x7FFFFFFF;

        auto exact_score = [&](int c) -> float {
            const float4* wp = (const float4*)(g_wT + (size_t)c * DIM);
            float a0 = 0.f, a1 = 0.f, a2 = 0.f, a3 = 0.f;
#pragma unroll 8
            for (int dq = 0; dq < DIM / 4; dq++) {
                float4 wv = __ldg(wp + dq);
                const int d = dq * 4;
                a0 = __fmaf_rn(zs[d * ZSTR + row], wv.x, a0);
                a1 = __fmaf_rn(zs[(d + 1) * ZSTR + row], wv.y, a1);
                a2 = __fmaf_rn(zs[(d + 2) * ZSTR + row], wv.z, a2);
                a3 = __fmaf_rn(zs[(d + 3) * ZSTR + row], wv.w, a3);
            }
            float dot = __fadd_rn(__fadd_rn(__fadd_rn(a0, a1), a2), a3);
            return __fsub_rn(__fadd_rn(zsqr, swsq[c]), __fmul_rn(2.f, dot));
        };

        if (cnt <= CAP) {
            for (int i = t4; i < cnt; i += 4) {
                int c = scand[row * CAP + i];
                float s = exact_score(c);
                if (s < bv || (s == bv && c < bi)) { bv = s; bi = c; }
            }
        } else {  // overflow: deterministic full scan
            for (int c = t4; c < KCODES; c += 4) {
                float s = exact_score(c);
                if (s < bv || (s == bv && c < bi)) { bv = s; bi = c; }
            }
        }
#pragma unroll
        for (int off = 1; off <= 2; off <<= 1) {
            float v2 = __shfl_xor_sync(0xffffffffu, bv, off);
            int   i2 = __shfl_xor_sync(0xffffffffu, bi, off);
            if (v2 < bv || (v2 == bv && i2 < bi)) { bv = v2; bi = i2; }
        }
        if (t4 == 0) srowidx[row] = bi;
    }
    __syncthreads();

    // ---- epilogue: gather code, q_st, losses ----
    const int r  = tid & 63;
    const int dh = tid >> 6;    // 0..3
    const int kstar = srowidx[r];
    const float* wrow = g_wT + (size_t)kstar * DIM;
    float* qb = qout + ((size_t)(b * DIM) << 10) + hw0;
    float partial = 0.f;
#pragma unroll 4
    for (int d = dh; d < DIM; d += 4) {
        float wv = __ldg(wrow + d);
        float zv = zs[d * ZSTR + r];
        float diff = __fsub_rn(wv, zv);
        partial = __fmaf_rn(diff, diff, partial);
        qb[((size_t)d << 10) + r] = __fadd_rn(zv, diff);  // z + (q - z)
    }
    part[tid] = partial;
    __syncthreads();
    if (dh == 0) {
        float mse = __fmul_rn(__fadd_rn(__fadd_rn(part[r], part[64 + r]),
                                        __fadd_rn(part[128 + r], part[192 + r])),
                              1.0f / DIM);
        int n = n0 + r;
        commit[n] = mse;
        embed[n]  = mse;
        loss[n]   = __fadd_rn(__fmul_rn(0.25f, mse), mse);
    }
}

// ---------------------------------------------------------------------------
extern "C" void kernel_launch(void* const* d_in, const int* in_sizes, int n_in,
                              void* d_out, int out_size) {
    const float* z = (const float*)d_in[0];
    const float* w = (const float*)d_in[1];
    float* out    = (float*)d_out;
    float* qout   = out;
    float* loss   = out + QOUT_ELEMS;
    float* commit = loss + LOSS_ELEMS;
    float* embed  = commit + LOSS_ELEMS;

    wsq_kernel<<<KCODES / 32, dim3(32, 8)>>>(w);
    wprep_kernel<<<dim3(32, 8), dim3(32, 32)>>>(w);
    zsq_kernel<<<N_TOTAL / 32, dim3(32, 32)>>>(z);

    const size_t smem_bytes =
        (size_t)(DIM * ZSTR + 32 * WSTR + KCODES) * sizeof(float) +
        (size_t)(BR * 2 + BR * CAP + BR) * sizeof(int) +
        (size_t)THREADS * sizeof(float);
    static bool attr_set = false;
    if (!attr_set) {
        cudaFuncSetAttribute(vq_kernel, cudaFuncAttributeMaxDynamicSharedMemorySize,
                             (int)smem_bytes);
        attr_set = true;
    }
    vq_kernel<<<N_TOTAL / BR, THREADS, smem_bytes>>>(z, w, qout, loss, commit, embed);
}

// round 10
// speedup vs baseline: 1.9501x; 1.4080x over previous
#include <cuda_runtime.h>
#include <cstdint>
#include <cfloat>

// Problem constants
#define N_TOTAL   32768
#define DIM       256
#define KCODES    1024
#define NTILES    512         // 64-row tiles
#define THREADS   256
#define GRID_VQ   296         // 148 SMs * 2 CTAs (occupancy-2 persistent grid)
#define ZSTR      72          // zs row stride (floats) >= 64; 72 % 32 == 8
#define CAP       32
#define EPSF      6e-3f       // >= 2x worst-case bf16 screening score error

#define QOUT_ELEMS   (32 * DIM * 32 * 32)
#define LOSS_ELEMS   N_TOTAL

// smem word offsets
#define W_ZS      0           // 256*72 = 18432
#define W_ZA      18432       // 16 rows * 72 = 1152 (bf16x2 fragments of z)
#define W_WSB     19584       // 16 rows * 136 = 2176 (bf16x2 codebook slab)
#define W_ROWMIN  21760       // 64
#define W_COUNT   21824       // 64
#define W_ROWIDX  21888       // 64
#define W_TILE    21952       // 1 (+pad)
#define W_CAND    21956       // 64*32 = 2048
#define SMEM_WORDS 24004      // 96016 bytes

__device__ float    g_wsq[KCODES];
__device__ float    g_zsq[N_TOTAL];
__device__ uint32_t g_wpk[(DIM / 2) * KCODES];  // bf16x2 pairs: (w[2e][c] lo, w[2e+1][c] hi)
__device__ float    g_wT[KCODES * DIM];         // transposed original w
__device__ int      g_tile_ctr;

__device__ __forceinline__ uint32_t pack_bf16x2(float lo, float hi) {
    uint32_t r;
    asm("cvt.rn.bf16x2.f32 %0, %1, %2;" : "=r"(r) : "f"(hi), "f"(lo));
    return r;
}
// m16n8k16 bf16 mma: D = A*B + D (fp32 accum)
__device__ __forceinline__ void mma_bf16(float* c, const uint32_t* a,
                                         uint32_t b0, uint32_t b1) {
    asm volatile(
        "mma.sync.aligned.m16n8k16.row.col.f32.bf16.bf16.f32 "
        "{%0,%1,%2,%3}, {%4,%5,%6,%7}, {%8,%9}, {%0,%1,%2,%3};"
        : "+f"(c[0]), "+f"(c[1]), "+f"(c[2]), "+f"(c[3])
        : "r"(a[0]), "r"(a[1]), "r"(a[2]), "r"(a[3]), "r"(b0), "r"(b1));
}

// ---------------------------------------------------------------------------
__global__ void reset_ctr_kernel() { g_tile_ctr = 0; }

// wsq[k] = sum_d w[d][k]^2
__global__ void __launch_bounds__(256)
wsq_kernel(const float* __restrict__ w) {
    __shared__ float red[8][32];
    const int tx = threadIdx.x, ty = threadIdx.y;
    const int k = blockIdx.x * 32 + tx;
    float s = 0.f;
#pragma unroll
    for (int i = 0; i < 32; i++) {
        float v = w[(size_t)(ty + 8 * i) * KCODES + k];
        s = __fadd_rn(s, __fmul_rn(v, v));
    }
    red[ty][tx] = s;
    __syncthreads();
    if (ty == 0) {
        float t = red[0][tx];
#pragma unroll
        for (int j = 1; j < 8; j++) t = __fadd_rn(t, red[j][tx]);
        g_wsq[k] = t;
    }
}

// w prep: g_wpk (bf16x2 d-pairs, same [d][c] order) + g_wT (transpose)
__global__ void __launch_bounds__(1024)
wprep_kernel(const float* __restrict__ w) {
    __shared__ float t[32][33];
    const int tx = threadIdx.x, ty = threadIdx.y;
    const int c0 = blockIdx.x * 32, d0 = blockIdx.y * 32;
    float v = w[(size_t)(d0 + ty) * KCODES + c0 + tx];
    t[ty][tx] = v;
    __syncthreads();
    g_wT[(size_t)(c0 + ty) * DIM + d0 + tx] = t[tx][ty];
    if (ty < 16) {
        const int e = (d0 >> 1) + ty;
        g_wpk[(size_t)e * KCODES + c0 + tx] = pack_bf16x2(t[2 * ty][tx], t[2 * ty + 1][tx]);
    }
}

// zsq[n] = sum_d z[n,d]^2
__global__ void __launch_bounds__(1024)
zsq_kernel(const float* __restrict__ z) {
    __shared__ float sp[32][33];
    const int tx = threadIdx.x, ty = threadIdx.y;
    const int n0 = blockIdx.x * 32;
    const int b  = n0 >> 10;
    const int hw = (n0 & 1023) + tx;
    const float* zb = z + ((size_t)(b * DIM) << 10) + hw;
    float p = 0.f;
#pragma unroll
    for (int i = 0; i < 8; i++) {
        float v = zb[(size_t)(ty + 32 * i) << 10];
        p = __fadd_rn(p, __fmul_rn(v, v));
    }
    sp[ty][tx] = p;
    __syncthreads();
    float val = sp[tx][ty];
#pragma unroll
    for (int off = 16; off >= 1; off >>= 1)
        val = __fadd_rn(val, __shfl_down_sync(0xffffffffu, val, off));
    if (tx == 0) g_zsq[n0 + ty] = val;
}

// ---------------------------------------------------------------------------
// Persistent fused kernel: bf16 screening GEMM + conservative collect
//   + exact fp32 rescue argmin + gather + q_st + losses.
// ---------------------------------------------------------------------------
__global__ void __launch_bounds__(THREADS, 2)
vq_kernel(const float* __restrict__ z, const float* __restrict__ w,
          float* __restrict__ qout, float* __restrict__ loss,
          float* __restrict__ commit, float* __restrict__ embed) {
    extern __shared__ float sm[];
    float*    zs      = sm + W_ZS;
    uint32_t* zA      = (uint32_t*)(sm + W_ZA);
    uint32_t* wsB     = (uint32_t*)(sm + W_WSB);
    int*      srowmin = (int*)(sm + W_ROWMIN);
    int*      scount  = (int*)(sm + W_COUNT);
    int*      srowidx = (int*)(sm + W_ROWIDX);
    int*      stile   = (int*)(sm + W_TILE);
    int*      scand   = (int*)(sm + W_CAND);
    float*    part    = (float*)scand;          // alias: used only in epilogue

    const int tid  = threadIdx.x;
    const int warp = tid >> 5;
    const int lane = tid & 31;
    const int wr = (warp & 1) * 32;
    const int wc = (warp >> 1) * 32;
    const int lg = lane >> 2;
    const int lt = lane & 3;

    for (;;) {
        if (tid == 0) stile[0] = atomicAdd(&g_tile_ctr, 1);
        __syncthreads();
        const int tile = stile[0];
        if (tile >= NTILES) break;

        const int n0  = tile * 64;
        const int b   = n0 >> 10;
        const int hw0 = n0 & 1023;
        const float* zbase = z + ((size_t)(b * DIM) << 10) + hw0;

        // ---- load z tile (fp32, kept for rescue/epilogue) ----
        for (int i = tid; i < DIM * 16; i += THREADS) {
            int d = i >> 4, f = i & 15;
            *(float4*)(zs + d * ZSTR + f * 4) =
                *(const float4*)(zbase + ((size_t)d << 10) + f * 4);
        }
        if (tid < 64) { srowmin[tid] = 0x7F7FFFFF; scount[tid] = 0; }

        float tzsq[4];
#pragma unroll
        for (int mi = 0; mi < 2; mi++)
#pragma unroll
            for (int h = 0; h < 2; h++)
                tzsq[mi * 2 + h] = g_zsq[n0 + wr + mi * 16 + h * 8 + lg];

        // ---- screening: 8 k-tiles of 128 codebook cols ----
        for (int kt = 0; kt < 8; kt++) {
            float acc[2][4][4];
#pragma unroll
            for (int mi = 0; mi < 2; mi++)
#pragma unroll
                for (int ni = 0; ni < 4; ni++)
#pragma unroll
                    for (int q = 0; q < 4; q++) acc[mi][ni][q] = 0.f;

            for (int stage = 0; stage < 8; stage++) {
                __syncthreads();   // prior readers of zA/wsB done (covers zs 1st)
                // stage zA: bf16x2 fragment layout, 2 tasks/thread
#pragma unroll
                for (int j = 0; j < 2; j++) {
                    const int p = tid + j * 256;
                    const int r = p & 63, plt = (p >> 6) & 3, pcc = p >> 8;
                    const int d0 = stage * 32 + pcc * 16 + plt * 2;
                    float z0 = zs[d0 * ZSTR + r];
                    float z1 = zs[(d0 + 1) * ZSTR + r];
                    float z2 = zs[(d0 + 8) * ZSTR + r];
                    float z3 = zs[(d0 + 9) * ZSTR + r];
                    zA[(pcc * 4 + plt) * 72 + r]       = pack_bf16x2(z0, z1);
                    zA[(8 + pcc * 4 + plt) * 72 + r]   = pack_bf16x2(z2, z3);
                }
                // stage wsB: pure uint4 copy of pre-packed codebook slab
#pragma unroll
                for (int j = 0; j < 2; j++) {
                    const int q = tid + j * 256;        // 512 uint4 tasks
                    const int c16 = q & 31, e = q >> 5; // e 0..15
                    uint4 v = *(const uint4*)(g_wpk
                        + (size_t)(stage * 16 + e) * KCODES + kt * 128 + c16 * 4);
                    *(uint4*)(wsB + e * 136 + c16 * 4) = v;
                }
                __syncthreads();

                // compute: 2 k16-chunks, 2 mtiles x 4 ntiles
#pragma unroll
                for (int cc = 0; cc < 2; cc++) {
                    uint32_t a[2][4];
#pragma unroll
                    for (int mi = 0; mi < 2; mi++) {
                        const int r0 = wr + mi * 16 + lg;
                        const int rlo = (cc * 4 + lt) * 72;
                        const int rhi = rlo + 8 * 72;
                        a[mi][0] = zA[rlo + r0];
                        a[mi][1] = zA[rlo + r0 + 8];
                        a[mi][2] = zA[rhi + r0];
                        a[mi][3] = zA[rhi + r0 + 8];
                    }
#pragma unroll
                    for (int ni = 0; ni < 4; ni++) {
                        const int col = wc + ni * 8 + lg;
                        uint32_t b0 = wsB[(cc * 8 + lt) * 136 + col];
                        uint32_t b1 = wsB[(cc * 8 + lt + 4) * 136 + col];
                        mma_bf16(acc[0][ni], a[0], b0, b1);
                        mma_bf16(acc[1][ni], a[1], b0, b1);
                    }
                }
            }

            // pass 1: per-row screened running min
#pragma unroll
            for (int mi = 0; mi < 2; mi++)
#pragma unroll
                for (int h = 0; h < 2; h++) {
                    const int idx = mi * 2 + h;
                    float rm = FLT_MAX;
#pragma unroll
                    for (int ni = 0; ni < 4; ni++) {
                        const int col0 = kt * 128 + wc + ni * 8 + lt * 2;
                        float s0 = __fsub_rn(__fadd_rn(tzsq[idx], __ldg(&g_wsq[col0])),
                                             __fmul_rn(2.f, acc[mi][ni][h * 2]));
                        float s1 = __fsub_rn(__fadd_rn(tzsq[idx], __ldg(&g_wsq[col0 + 1])),
                                             __fmul_rn(2.f, acc[mi][ni][h * 2 + 1]));
                        rm = fminf(rm, fminf(s0, s1));
                    }
                    rm = fminf(rm, __shfl_xor_sync(0xffffffffu, rm, 1));
                    rm = fminf(rm, __shfl_xor_sync(0xffffffffu, rm, 2));
                    if (lt == 0)
                        atomicMin(&srowmin[wr + mi * 16 + h * 8 + lg],
                                  __float_as_int(rm));
                }
            __syncthreads();

            // pass 2: collect candidates <= running row min + EPS
#pragma unroll
            for (int mi = 0; mi < 2; mi++)
#pragma unroll
                for (int h = 0; h < 2; h++) {
                    const int idx = mi * 2 + h;
                    const int row = wr + mi * 16 + h * 8 + lg;
                    const float thr = __int_as_float(srowmin[row]) + EPSF;
#pragma unroll
                    for (int ni = 0; ni < 4; ni++) {
                        const int col0 = kt * 128 + wc + ni * 8 + lt * 2;
                        float s0 = __fsub_rn(__fadd_rn(tzsq[idx], __ldg(&g_wsq[col0])),
                                             __fmul_rn(2.f, acc[mi][ni][h * 2]));
                        float s1 = __fsub_rn(__fadd_rn(tzsq[idx], __ldg(&g_wsq[col0 + 1])),
                                             __fmul_rn(2.f, acc[mi][ni][h * 2 + 1]));
                        if (s0 <= thr) {
                            int p = atomicAdd(&scount[row], 1);
                            if (p < CAP) scand[row * CAP + p] = col0;
                        }
                        if (s1 <= thr) {
                            int p = atomicAdd(&scount[row], 1);
                            if (p < CAP) scand[row * CAP + p] = col0 + 1;
                        }
                    }
                }
        }
        __syncthreads();

        // ---- exact rescue: 4 threads per row, fp32, exact bucketing ----
        {
            const int row = tid >> 2;
            const int t4  = tid & 3;
            const int cnt = scount[row];
            const float zsqr = g_zsq[n0 + row];
            float bv = FLT_MAX;
            int   bi = 0x7FFFFFFF;

            auto exact_score = [&](int c) -> float {
                const float4* wp = (const float4*)(g_wT + (size_t)c * DIM);
                float a0 = 0.f, a1 = 0.f, a2 = 0.f, a3 = 0.f;
#pragma unroll 8
                for (int dq = 0; dq < DIM / 4; dq++) {
                    float4 wv = __ldg(wp + dq);
                    const int d = dq * 4;
                    a0 = __fmaf_rn(zs[d * ZSTR + row], wv.x, a0);
                    a1 = __fmaf_rn(zs[(d + 1) * ZSTR + row], wv.y, a1);
                    a2 = __fmaf_rn(zs[(d + 2) * ZSTR + row], wv.z, a2);
                    a3 = __fmaf_rn(zs[(d + 3) * ZSTR + row], wv.w, a3);
                }
                float dot = __fadd_rn(__fadd_rn(__fadd_rn(a0, a1), a2), a3);
                return __fsub_rn(__fadd_rn(zsqr, __ldg(&g_wsq[c])),
                                 __fmul_rn(2.f, dot));
            };

            if (cnt <= CAP) {
                for (int i = t4; i < cnt; i += 4) {
                    int c = scand[row * CAP + i];
                    float s = exact_score(c);
                    if (s < bv || (s == bv && c < bi)) { bv = s; bi = c; }
                }
            } else {  // overflow: deterministic full scan
                for (int c = t4; c < KCODES; c += 4) {
                    float s = exact_score(c);
                    if (s < bv || (s == bv && c < bi)) { bv = s; bi = c; }
                }
            }
#pragma unroll
            for (int off = 1; off <= 2; off <<= 1) {
                float v2 = __shfl_xor_sync(0xffffffffu, bv, off);
                int   i2 = __shfl_xor_sync(0xffffffffu, bi, off);
                if (v2 < bv || (v2 == bv && i2 < bi)) { bv = v2; bi = i2; }
            }
            if (t4 == 0) srowidx[row] = bi;
        }
        __syncthreads();

        // ---- epilogue: gather code, q_st, losses ----
        const int r  = tid & 63;
        const int dh = tid >> 6;    // 0..3
        const int kstar = srowidx[r];
        const float* wrow = g_wT + (size_t)kstar * DIM;
        float* qb = qout + ((size_t)(b * DIM) << 10) + hw0;
        float partial = 0.f;
#pragma unroll 4
        for (int d = dh; d < DIM; d += 4) {
            float wv = __ldg(wrow + d);
            float zv = zs[d * ZSTR + r];
            float diff = __fsub_rn(wv, zv);
            partial = __fmaf_rn(diff, diff, partial);
            qb[((size_t)d << 10) + r] = __fadd_rn(zv, diff);  // z + (q - z)
        }
        part[tid] = partial;
        __syncthreads();
        if (dh == 0) {
            float mse = __fmul_rn(
                __fadd_rn(__fadd_rn(part[r], part[64 + r]),
                          __fadd_rn(part[128 + r], part[192 + r])),
                1.0f / DIM);
            int n = n0 + r;
            commit[n] = mse;
            embed[n]  = mse;
            loss[n]   = __fadd_rn(__fmul_rn(0.25f, mse), mse);
        }
        __syncthreads();   // smem reuse barrier before next tile
    }
}

// ---------------------------------------------------------------------------
extern "C" void kernel_launch(void* const* d_in, const int* in_sizes, int n_in,
                              void* d_out, int out_size) {
    const float* z = (const float*)d_in[0];
    const float* w = (const float*)d_in[1];
    float* out    = (float*)d_out;
    float* qout   = out;
    float* loss   = out + QOUT_ELEMS;
    float* commit = loss + LOSS_ELEMS;
    float* embed  = commit + LOSS_ELEMS;

    reset_ctr_kernel<<<1, 1>>>();
    wsq_kernel<<<KCODES / 32, dim3(32, 8)>>>(w);
    wprep_kernel<<<dim3(32, 8), dim3(32, 32)>>>(w);
    zsq_kernel<<<N_TOTAL / 32, dim3(32, 32)>>>(z);

    const size_t smem_bytes = SMEM_WORDS * sizeof(float);
    static bool attr_set = false;
    if (!attr_set) {
        cudaFuncSetAttribute(vq_kernel, cudaFuncAttributeMaxDynamicSharedMemorySize,
                             (int)smem_bytes);
        attr_set = true;
    }
    vq_kernel<<<GRID_VQ, THREADS, smem_bytes>>>(z, w, qout, loss, commit, embed);
}